// round 11
// baseline (speedup 1.0000x reference)
#include <cuda_runtime.h>

// Net_58712202936903 — fused 2-layer multiplicative MLP, fp32, FFMA-bound.
// Round 10 (ninth resubmit — rounds 2-10 all hit broker GPUAcquisitionTimeout;
// this kernel has never executed). Single persistent kernel, 512 threads
// (16 warps/SM), vectorized layer-1, unified tile space (fwd T, fwd center, JVP l).
//
// Outputs (concat): v_t[65536], v_y[65536], v_grad[65536], v_center[512].
// v_grad computed as forward-mode JVP with tangent l1_dot (no Jacobian).

#define H    128
#define NIN  8
#define WST  132   // layer-2 transposed weight stride (float4-aligned, conflict-free col reads)
#define YST  132   // Y buffer stride (float4-aligned)

// smem (floats):
//  sW1t 128*132=16896 | sW2t 16896 | sW11t 8*128=1024 | sW21t 1024 | sb11 128 | sb21 128
//  sY 128*132=16896 (fwd TB=128; jvp splits it: sY 64*132 + sYd 64*132)
//  sX 1024 (fwd 128*8; jvp: sX 512 + sXd 512)
#define SMEM_FLOATS (16896*3 + 1024*2 + 128*2 + 1024)
#define SMEM_BYTES  (SMEM_FLOATS * 4)

__device__ __forceinline__ float warp_sum(float v) {
    v += __shfl_xor_sync(0xffffffffu, v, 16);
    v += __shfl_xor_sync(0xffffffffu, v, 8);
    v += __shfl_xor_sync(0xffffffffu, v, 4);
    v += __shfl_xor_sync(0xffffffffu, v, 2);
    v += __shfl_xor_sync(0xffffffffu, v, 1);
    return v;
}

extern "C" __global__ void __launch_bounds__(512, 1)
net_all_kernel(const float* __restrict__ T, const float* __restrict__ l,
               const float* __restrict__ ldot, const float* __restrict__ center,
               int nT, int nC,
               float* __restrict__ out_vt, float* __restrict__ out_vy,
               float* __restrict__ out_vg, float* __restrict__ out_vc,
               const float* __restrict__ W11, const float* __restrict__ b11,
               const float* __restrict__ W21, const float* __restrict__ b21,
               const float* __restrict__ W12, const float* __restrict__ b12,
               const float* __restrict__ W22, const float* __restrict__ b22,
               const float* __restrict__ wout)
{
    extern __shared__ float smem[];
    float* sW1t  = smem;                  // [k][o] stride WST
    float* sW2t  = sW1t  + H * WST;
    float* sW11t = sW2t  + H * WST;       // [j][h]
    float* sW21t = sW11t + NIN * H;
    float* sb11  = sW21t + NIN * H;
    float* sb21  = sb11  + H;
    float* sY    = sb21  + H;             // TB * YST
    float* sX    = sY    + H * YST;       // 1024 floats

    const int t  = threadIdx.x;
    const int tx = t & 31;
    const int ty = t >> 5;

    // ---- stage weights (once per block) ----
    for (int i = t; i < H * H; i += 512) {
        int o = i >> 7, k = i & (H - 1);        // global read coalesced over k
        sW1t[k * WST + o] = W12[i];
        sW2t[k * WST + o] = W22[i];
    }
    for (int i = t; i < H * NIN; i += 512) {
        int h = i >> 3, j = i & (NIN - 1);
        sW11t[j * H + h] = W11[i];
        sW21t[j * H + h] = W21[i];
    }
    if (t < H) { sb11[t] = b11[t]; sb21[t] = b21[t]; }

    float rb1[4], rb2[4], wo[4];
#pragma unroll
    for (int oo = 0; oo < 4; oo++) {
        rb1[oo] = b12[4 * tx + oo];
        rb2[oo] = b22[4 * tx + oo];
        wo[oo]  = wout[4 * tx + oo];
    }

    const int ntT = nT >> 7;          // fwd tiles of 128 (T)
    const int ntC = nC >> 7;          // fwd tiles of 128 (center)
    const int ntF = ntT + ntC;
    const int ntJ = nT >> 6;          // jvp tiles of 64
    const int total = ntF + ntJ;

    for (int tile = blockIdx.x; tile < total; tile += gridDim.x) {
        if (tile < ntF) {
            // ================= FORWARD tile (TB = 128) =================
            const float* xsrc; float* osrc; int base;
            if (tile < ntT) { xsrc = T;      osrc = out_vt; base = tile * 128; }
            else            { xsrc = center; osrc = out_vc; base = (tile - ntT) * 128; }

            __syncthreads();   // previous tile's smem readers done
            {
                const float4* src = (const float4*)(xsrc + base * NIN);
                float4* dst = (float4*)sX;
                for (int i = t; i < 128 * NIN / 4; i += 512) dst[i] = src[i];
            }
            __syncthreads();

            // layer 1: thread handles (sample s, 4 consecutive h)
            for (int g = t; g < 128 * (H / 4); g += 512) {
                int hq = g & 31, s = g >> 5;            // warp: hq varies, s fixed -> x broadcast
                const float* xp = sX + s * NIN;
                float4 xa = *(const float4*)(xp);
                float4 xb = *(const float4*)(xp + 4);
                float xr[8] = { xa.x, xa.y, xa.z, xa.w, xb.x, xb.y, xb.z, xb.w };
                float4 z1 = *(const float4*)(sb11 + 4 * hq);
                float4 z2 = *(const float4*)(sb21 + 4 * hq);
                float z1a[4] = { z1.x, z1.y, z1.z, z1.w };
                float z2a[4] = { z2.x, z2.y, z2.z, z2.w };
#pragma unroll
                for (int j = 0; j < NIN; j++) {
                    float4 w1 = *(const float4*)(sW11t + j * H + 4 * hq);
                    float4 w2 = *(const float4*)(sW21t + j * H + 4 * hq);
                    float xj = xr[j];
                    z1a[0] += w1.x * xj; z1a[1] += w1.y * xj;
                    z1a[2] += w1.z * xj; z1a[3] += w1.w * xj;
                    z2a[0] += w2.x * xj; z2a[1] += w2.y * xj;
                    z2a[2] += w2.z * xj; z2a[3] += w2.w * xj;
                }
                float4 yv = { z1a[0] * z2a[0], z1a[1] * z2a[1],
                              z1a[2] * z2a[2], z1a[3] * z2a[3] };
                *(float4*)(sY + s * YST + 4 * hq) = yv;
            }
            __syncthreads();

            // layer 2: thread (tx,ty) -> o = 4tx..4tx+3, s = 8ty..8ty+7
            float a1[8][4], a2[8][4];
#pragma unroll
            for (int ss = 0; ss < 8; ss++)
#pragma unroll
                for (int oo = 0; oo < 4; oo++) { a1[ss][oo] = rb1[oo]; a2[ss][oo] = rb2[oo]; }

            const float* yrow = sY + (ty * 8) * YST;
#pragma unroll 1
            for (int k = 0; k < H; k += 2) {
                float4 v;
                float w1a[4], w1b[4], w2a[4], w2b[4];
                v = *(const float4*)(sW1t + k * WST + 4 * tx);
                w1a[0] = v.x; w1a[1] = v.y; w1a[2] = v.z; w1a[3] = v.w;
                v = *(const float4*)(sW1t + (k + 1) * WST + 4 * tx);
                w1b[0] = v.x; w1b[1] = v.y; w1b[2] = v.z; w1b[3] = v.w;
                v = *(const float4*)(sW2t + k * WST + 4 * tx);
                w2a[0] = v.x; w2a[1] = v.y; w2a[2] = v.z; w2a[3] = v.w;
                v = *(const float4*)(sW2t + (k + 1) * WST + 4 * tx);
                w2b[0] = v.x; w2b[1] = v.y; w2b[2] = v.z; w2b[3] = v.w;
#pragma unroll
                for (int ss = 0; ss < 8; ss++) {
                    float2 yv = *(const float2*)(yrow + ss * YST + k);   // broadcast
#pragma unroll
                    for (int oo = 0; oo < 4; oo++) {
                        a1[ss][oo] += w1a[oo] * yv.x + w1b[oo] * yv.y;
                        a2[ss][oo] += w2a[oo] * yv.x + w2b[oo] * yv.y;
                    }
                }
            }

#pragma unroll
            for (int ss = 0; ss < 8; ss++) {
                float p = 0.f;
#pragma unroll
                for (int oo = 0; oo < 4; oo++) p += wo[oo] * a1[ss][oo] * a2[ss][oo];
                p = warp_sum(p);
                if (tx == 0) osrc[base + ty * 8 + ss] = p;
            }
        } else {
            // ================= JVP tile (TB = 64) =================
            const int base = (tile - ntF) * 64;
            float* sYd = sY + 64 * YST;
            float* sXd = sX + 512;

            __syncthreads();
            {
                const float4* sv = (const float4*)(l    + base * NIN);
                const float4* sd = (const float4*)(ldot + base * NIN);
                float4* dv = (float4*)sX;
                float4* dd = (float4*)sXd;
                for (int i = t; i < 64 * NIN / 4; i += 512) { dv[i] = sv[i]; dd[i] = sd[i]; }
            }
            __syncthreads();

            // layer 1 + tangent
            for (int g = t; g < 64 * (H / 4); g += 512) {
                int hq = g & 31, s = g >> 5;
                const float* xp  = sX  + s * NIN;
                const float* xdp = sXd + s * NIN;
                float4 xa = *(const float4*)(xp);
                float4 xb = *(const float4*)(xp + 4);
                float4 da = *(const float4*)(xdp);
                float4 db = *(const float4*)(xdp + 4);
                float xr[8]  = { xa.x, xa.y, xa.z, xa.w, xb.x, xb.y, xb.z, xb.w };
                float xdr[8] = { da.x, da.y, da.z, da.w, db.x, db.y, db.z, db.w };
                float4 zb1 = *(const float4*)(sb11 + 4 * hq);
                float4 zb2 = *(const float4*)(sb21 + 4 * hq);
                float z1a[4] = { zb1.x, zb1.y, zb1.z, zb1.w };
                float z2a[4] = { zb2.x, zb2.y, zb2.z, zb2.w };
                float d1a[4] = { 0.f, 0.f, 0.f, 0.f };
                float d2a[4] = { 0.f, 0.f, 0.f, 0.f };
#pragma unroll
                for (int j = 0; j < NIN; j++) {
                    float4 w1 = *(const float4*)(sW11t + j * H + 4 * hq);
                    float4 w2 = *(const float4*)(sW21t + j * H + 4 * hq);
                    float w1r[4] = { w1.x, w1.y, w1.z, w1.w };
                    float w2r[4] = { w2.x, w2.y, w2.z, w2.w };
                    float xj = xr[j], xdj = xdr[j];
#pragma unroll
                    for (int c = 0; c < 4; c++) {
                        z1a[c] += w1r[c] * xj;
                        z2a[c] += w2r[c] * xj;
                        d1a[c] += w1r[c] * xdj;
                        d2a[c] += w2r[c] * xdj;
                    }
                }
                float4 yv, ydv;
                yv.x  = z1a[0] * z2a[0]; yv.y  = z1a[1] * z2a[1];
                yv.z  = z1a[2] * z2a[2]; yv.w  = z1a[3] * z2a[3];
                ydv.x = z1a[0] * d2a[0] + z2a[0] * d1a[0];
                ydv.y = z1a[1] * d2a[1] + z2a[1] * d1a[1];
                ydv.z = z1a[2] * d2a[2] + z2a[2] * d1a[2];
                ydv.w = z1a[3] * d2a[3] + z2a[3] * d1a[3];
                *(float4*)(sY  + s * YST + 4 * hq) = yv;
                *(float4*)(sYd + s * YST + 4 * hq) = ydv;
            }
            __syncthreads();

            // layer 2: value + tangent. thread -> o = 4tx..4tx+3, s = 4ty..4ty+3
            float a1[4][4], a2[4][4], g1[4][4], g2[4][4];
#pragma unroll
            for (int ss = 0; ss < 4; ss++)
#pragma unroll
                for (int oo = 0; oo < 4; oo++) {
                    a1[ss][oo] = rb1[oo]; a2[ss][oo] = rb2[oo];
                    g1[ss][oo] = 0.f;     g2[ss][oo] = 0.f;
                }

            const float* yrow  = sY  + (ty * 4) * YST;
            const float* ydrow = sYd + (ty * 4) * YST;
#pragma unroll 1
            for (int k = 0; k < H; k += 2) {
                float4 v;
                float w1a[4], w1b[4], w2a[4], w2b[4];
                v = *(const float4*)(sW1t + k * WST + 4 * tx);
                w1a[0] = v.x; w1a[1] = v.y; w1a[2] = v.z; w1a[3] = v.w;
                v = *(const float4*)(sW1t + (k + 1) * WST + 4 * tx);
                w1b[0] = v.x; w1b[1] = v.y; w1b[2] = v.z; w1b[3] = v.w;
                v = *(const float4*)(sW2t + k * WST + 4 * tx);
                w2a[0] = v.x; w2a[1] = v.y; w2a[2] = v.z; w2a[3] = v.w;
                v = *(const float4*)(sW2t + (k + 1) * WST + 4 * tx);
                w2b[0] = v.x; w2b[1] = v.y; w2b[2] = v.z; w2b[3] = v.w;
#pragma unroll
                for (int ss = 0; ss < 4; ss++) {
                    float2 yv  = *(const float2*)(yrow  + ss * YST + k);  // broadcast
                    float2 ydv = *(const float2*)(ydrow + ss * YST + k);
#pragma unroll
                    for (int oo = 0; oo < 4; oo++) {
                        a1[ss][oo] += w1a[oo] * yv.x  + w1b[oo] * yv.y;
                        a2[ss][oo] += w2a[oo] * yv.x  + w2b[oo] * yv.y;
                        g1[ss][oo] += w1a[oo] * ydv.x + w1b[oo] * ydv.y;
                        g2[ss][oo] += w2a[oo] * ydv.x + w2b[oo] * ydv.y;
                    }
                }
            }

#pragma unroll
            for (int ss = 0; ss < 4; ss++) {
                float pv = 0.f, pg = 0.f;
#pragma unroll
                for (int oo = 0; oo < 4; oo++) {
                    pv += wo[oo] * a1[ss][oo] * a2[ss][oo];
                    pg += wo[oo] * (g1[ss][oo] * a2[ss][oo] + a1[ss][oo] * g2[ss][oo]);
                }
                pv = warp_sum(pv);
                pg = warp_sum(pg);
                if (tx == 0) {
                    out_vy[base + ty * 4 + ss] = pv;
                    out_vg[base + ty * 4 + ss] = pg;
                }
            }
        }
    }
}

// ---------------------------------------------------------------------------
extern "C" void kernel_launch(void* const* d_in, const int* in_sizes, int n_in,
                              void* d_out, int out_size)
{
    const float* T      = (const float*)d_in[0];
    const float* l      = (const float*)d_in[1];
    const float* l1_dot = (const float*)d_in[2];
    const float* center = (const float*)d_in[3];
    const float* w11    = (const float*)d_in[4];
    const float* b11    = (const float*)d_in[5];
    const float* w21    = (const float*)d_in[6];
    const float* b21    = (const float*)d_in[7];
    const float* w12    = (const float*)d_in[8];
    const float* b12    = (const float*)d_in[9];
    const float* w22    = (const float*)d_in[10];
    const float* b22    = (const float*)d_in[11];
    const float* wout   = (const float*)d_in[12];

    const int nT = in_sizes[0] / NIN;   // 65536
    const int nC = in_sizes[3] / NIN;   // 512

    float* out    = (float*)d_out;
    float* out_vt = out;
    float* out_vy = out + nT;
    float* out_vg = out + 2 * nT;
    float* out_vc = out + 3 * nT;

    cudaFuncSetAttribute(net_all_kernel, cudaFuncAttributeMaxDynamicSharedMemorySize, SMEM_BYTES);

    net_all_kernel<<<148, 512, SMEM_BYTES>>>(T, l, l1_dot, center, nT, nC,
                                             out_vt, out_vy, out_vg, out_vc,
                                             w11, b11, w21, b21,
                                             w12, b12, w22, b22, wout);
}